// round 9
// baseline (speedup 1.0000x reference)
#include <cuda_runtime.h>
#include <math.h>

#define NROWS 8192
#define KIN   512
#define HD    256
#define WD    64
#define BK    8
#define BM    32      // rows per CTA
#define TM    8       // rows per thread
#define TN    8       // cols per thread (stage 1/2)
#define BSW_STRIDE 66 // bank step 2 -> conflict-free u64 LDS (was 68 = 4-way)

// ---------------------------------------------------------------------------
// f32x2 packed helpers (FFMA2: 2 MACs per instruction on sm_103a)
// ---------------------------------------------------------------------------
__device__ __forceinline__ unsigned long long pack_ff(float a) {
    unsigned long long r;
    unsigned int u = __float_as_uint(a);
    asm("mov.b64 %0, {%1, %1};" : "=l"(r) : "r"(u));
    return r;
}
__device__ __forceinline__ void ffma2(unsigned long long &c,
                                      unsigned long long a,
                                      unsigned long long b) {
    asm("fma.rn.f32x2 %0, %1, %2, %0;" : "+l"(c) : "l"(a), "l"(b));
}
__device__ __forceinline__ float2 unpack_ff(unsigned long long v) {
    unsigned int lo, hi;
    asm("mov.b64 {%0, %1}, %2;" : "=r"(lo), "=r"(hi) : "l"(v));
    float2 f;
    f.x = __uint_as_float(lo);
    f.y = __uint_as_float(hi);
    return f;
}

// ---------------------------------------------------------------------------
// Fully fused network: per CTA, 32 rows flow through all three layers.
//   h1 = relu(X@W1+b1)  -> smem
//   h2 = relu(h1@W2+b2) -> smem (overwrites h1)
//   out += sum( tanh(h2@Wq+bq) * Wh )   [mean neighbor weight == 1.0]
// 128 threads: tx = lane (32 col-blocks of 8), ty = warp (4 row-groups of 8).
// Weight slab layout: BsW[colblk*66 + kk*8 + within] -> u64 reads hit all 32
// banks exactly once per 16-lane phase (conflict-free).
// ---------------------------------------------------------------------------
__global__ void __launch_bounds__(128, 2) fused_net(
    const float* __restrict__ X,
    const float* __restrict__ W1, const float* __restrict__ b1,
    const float* __restrict__ W2, const float* __restrict__ b2,
    const float* __restrict__ Wq, const float* __restrict__ bq,
    const float* __restrict__ Wh, float* __restrict__ out)
{
    __shared__ __align__(16) float h1s[BM * HD];           // 32 KB activations
    __shared__ __align__(16) float BsW[32 * BSW_STRIDE];   // swizzled weight slab
    __shared__ __align__(16) float Bs3[BK * WD];           // stage-3 Wq slab
    __shared__ __align__(16) float As1[BM * BK];           // stage-1 X slab
    __shared__ float red[4];

    const int tid = threadIdx.x;
    const int tx  = tid & 31;
    const int ty  = tid >> 5;
    const int rowBase = blockIdx.x * BM;

    // loader mappings
    const int aRow = tid >> 1;                 // 0..63 (tid<64 used)
    const int aK   = (tid & 1) * 4;
    const int lcol = (tid & 63) * 4;           // weight col
    const int cbS  = (lcol >> 3) * BSW_STRIDE + (lcol & 7);  // swizzled dest
    const int rowG = (tid >> 6) * 4;           // 0 or 4
    const int wRow = tid >> 4;                 // 0..7 (stage 3)
    const int wCol = (tid & 15) * 4;

    unsigned long long acc[TM][TN / 2];

    // ======================= stage 1: h1 = relu(X@W1+b1), K=512 ============
    #pragma unroll
    for (int i = 0; i < TM; i++)
        #pragma unroll
        for (int j = 0; j < TN / 2; j++) acc[i][j] = 0ull;

    float4 pa;
    float4 pb[4];
    if (tid < 64)
        pa = *(const float4*)(X + (long)(rowBase + aRow) * KIN + aK);
    #pragma unroll
    for (int r = 0; r < 4; r++)
        pb[r] = *(const float4*)(W1 + (long)(rowG + r) * HD + lcol);

    for (int k0 = 0; k0 < KIN; k0 += BK) {
        if (tid < 64) *(float4*)&As1[aRow * BK + aK] = pa;
        #pragma unroll
        for (int r = 0; r < 4; r++) {
            *(float2*)&BsW[cbS + (rowG + r) * 8]     = make_float2(pb[r].x, pb[r].y);
            *(float2*)&BsW[cbS + (rowG + r) * 8 + 2] = make_float2(pb[r].z, pb[r].w);
        }
        __syncthreads();

        if (k0 + BK < KIN) {
            if (tid < 64)
                pa = *(const float4*)(X + (long)(rowBase + aRow) * KIN + k0 + BK + aK);
            #pragma unroll
            for (int r = 0; r < 4; r++)
                pb[r] = *(const float4*)(W1 + (long)(k0 + BK + rowG + r) * HD + lcol);
        }

        #pragma unroll
        for (int kp = 0; kp < BK / 2; kp++) {
            float2 ap[TM];
            #pragma unroll
            for (int i = 0; i < TM; i++)
                ap[i] = *(const float2*)&As1[(ty * TM + i) * BK + 2 * kp];
            #pragma unroll
            for (int q = 0; q < 2; q++) {
                const int kk = 2 * kp + q;
                unsigned long long b2[TN / 2];
                #pragma unroll
                for (int j = 0; j < TN / 2; j++)
                    b2[j] = *(const unsigned long long*)
                                &BsW[tx * BSW_STRIDE + kk * 8 + 2 * j];
                #pragma unroll
                for (int i = 0; i < TM; i++) {
                    unsigned long long a2 = pack_ff(q ? ap[i].y : ap[i].x);
                    #pragma unroll
                    for (int j = 0; j < TN / 2; j++) ffma2(acc[i][j], a2, b2[j]);
                }
            }
        }
        __syncthreads();
    }

    // prefetch first W2 slab (overlap with epilogue)
    #pragma unroll
    for (int r = 0; r < 4; r++)
        pb[r] = *(const float4*)(W2 + (long)(rowG + r) * HD + lcol);

    // epilogue 1 -> h1s
    {
        const int c = tx * 8;
        const float4 bva = *(const float4*)&b1[c];
        const float4 bvb = *(const float4*)&b1[c + 4];
        #pragma unroll
        for (int i = 0; i < TM; i++) {
            const int r = ty * TM + i;
            float2 v0 = unpack_ff(acc[i][0]);
            float2 v1 = unpack_ff(acc[i][1]);
            float2 v2 = unpack_ff(acc[i][2]);
            float2 v3 = unpack_ff(acc[i][3]);
            float4 o0 = make_float4(fmaxf(v0.x + bva.x, 0.f), fmaxf(v0.y + bva.y, 0.f),
                                    fmaxf(v1.x + bva.z, 0.f), fmaxf(v1.y + bva.w, 0.f));
            float4 o1 = make_float4(fmaxf(v2.x + bvb.x, 0.f), fmaxf(v2.y + bvb.y, 0.f),
                                    fmaxf(v3.x + bvb.z, 0.f), fmaxf(v3.y + bvb.w, 0.f));
            *(float4*)&h1s[r * HD + c]     = o0;
            *(float4*)&h1s[r * HD + c + 4] = o1;
        }
    }
    __syncthreads();

    // ======================= stage 2: h2 = relu(h1@W2+b2), K=256 ===========
    #pragma unroll
    for (int i = 0; i < TM; i++)
        #pragma unroll
        for (int j = 0; j < TN / 2; j++) acc[i][j] = 0ull;

    for (int k0 = 0; k0 < HD; k0 += BK) {
        #pragma unroll
        for (int r = 0; r < 4; r++) {
            *(float2*)&BsW[cbS + (rowG + r) * 8]     = make_float2(pb[r].x, pb[r].y);
            *(float2*)&BsW[cbS + (rowG + r) * 8 + 2] = make_float2(pb[r].z, pb[r].w);
        }
        __syncthreads();

        if (k0 + BK < HD) {
            #pragma unroll
            for (int r = 0; r < 4; r++)
                pb[r] = *(const float4*)(W2 + (long)(k0 + BK + rowG + r) * HD + lcol);
        }

        #pragma unroll
        for (int kp = 0; kp < BK / 2; kp++) {
            float2 ap[TM];
            #pragma unroll
            for (int i = 0; i < TM; i++)
                ap[i] = *(const float2*)&h1s[(ty * TM + i) * HD + k0 + 2 * kp];
            #pragma unroll
            for (int q = 0; q < 2; q++) {
                const int kk = 2 * kp + q;
                unsigned long long b2[TN / 2];
                #pragma unroll
                for (int j = 0; j < TN / 2; j++)
                    b2[j] = *(const unsigned long long*)
                                &BsW[tx * BSW_STRIDE + kk * 8 + 2 * j];
                #pragma unroll
                for (int i = 0; i < TM; i++) {
                    unsigned long long a2 = pack_ff(q ? ap[i].y : ap[i].x);
                    #pragma unroll
                    for (int j = 0; j < TN / 2; j++) ffma2(acc[i][j], a2, b2[j]);
                }
            }
        }
        __syncthreads();
    }

    // prefetch first Wq slab
    float4 pw = *(const float4*)(Wq + (long)wRow * WD + wCol);

    // epilogue 2 -> h1s (all stage-2 reads are done: loop ended on a sync)
    {
        const int c = tx * 8;
        const float4 bva = *(const float4*)&b2[c];
        const float4 bvb = *(const float4*)&b2[c + 4];
        #pragma unroll
        for (int i = 0; i < TM; i++) {
            const int r = ty * TM + i;
            float2 v0 = unpack_ff(acc[i][0]);
            float2 v1 = unpack_ff(acc[i][1]);
            float2 v2 = unpack_ff(acc[i][2]);
            float2 v3 = unpack_ff(acc[i][3]);
            float4 o0 = make_float4(fmaxf(v0.x + bva.x, 0.f), fmaxf(v0.y + bva.y, 0.f),
                                    fmaxf(v1.x + bva.z, 0.f), fmaxf(v1.y + bva.w, 0.f));
            float4 o1 = make_float4(fmaxf(v2.x + bvb.x, 0.f), fmaxf(v2.y + bvb.y, 0.f),
                                    fmaxf(v3.x + bvb.z, 0.f), fmaxf(v3.y + bvb.w, 0.f));
            *(float4*)&h1s[r * HD + c]     = o0;
            *(float4*)&h1s[r * HD + c + 4] = o1;
        }
    }
    __syncthreads();

    // ======== stage 3: out += sum(tanh(h2@Wq+bq)*Wh), K=256, N=64 ==========
    unsigned long long acc3[TM];
    #pragma unroll
    for (int i = 0; i < TM; i++) acc3[i] = 0ull;

    for (int k0 = 0; k0 < HD; k0 += BK) {
        *(float4*)&Bs3[wRow * WD + wCol] = pw;
        __syncthreads();

        if (k0 + BK < HD)
            pw = *(const float4*)(Wq + (long)(k0 + BK + wRow) * WD + wCol);

        #pragma unroll
        for (int kp = 0; kp < BK / 2; kp++) {
            float2 ap[TM];
            #pragma unroll
            for (int i = 0; i < TM; i++)
                ap[i] = *(const float2*)&h1s[(ty * TM + i) * HD + k0 + 2 * kp];
            #pragma unroll
            for (int q = 0; q < 2; q++) {
                const int kk = 2 * kp + q;
                unsigned long long b2 =
                    *(const unsigned long long*)&Bs3[kk * WD + tx * 2];
                #pragma unroll
                for (int i = 0; i < TM; i++) {
                    unsigned long long a2 = pack_ff(q ? ap[i].y : ap[i].x);
                    ffma2(acc3[i], a2, b2);
                }
            }
        }
        __syncthreads();
    }

    // epilogue 3: tanh + dot Wh + block reduce + atomicAdd
    {
        const float2 bqv = *(const float2*)&bq[tx * 2];
        const float2 whv = *(const float2*)&Wh[tx * 2];
        float s = 0.f;
        #pragma unroll
        for (int i = 0; i < TM; i++) {
            float2 v = unpack_ff(acc3[i]);
            s += tanhf(v.x + bqv.x) * whv.x;
            s += tanhf(v.y + bqv.y) * whv.y;
        }
        #pragma unroll
        for (int o = 16; o > 0; o >>= 1)
            s += __shfl_down_sync(0xffffffffu, s, o);
        if (tx == 0) red[ty] = s;
        __syncthreads();
        if (tid == 0)
            atomicAdd(out, red[0] + red[1] + red[2] + red[3]);
    }
}

__global__ void init_out(float* __restrict__ out, const float* __restrict__ bh)
{
    if (threadIdx.x == 0) out[0] = bh[0];
}

// ---------------------------------------------------------------------------
// kernel_launch
// inputs (metadata order): state_batch, W1, b1, W2, b2, Wq, bq, Wh, bh
// ---------------------------------------------------------------------------
extern "C" void kernel_launch(void* const* d_in, const int* in_sizes, int n_in,
                              void* d_out, int out_size)
{
    const float* X  = (const float*)d_in[0];
    const float* W1 = (const float*)d_in[1];
    const float* b1 = (const float*)d_in[2];
    const float* W2 = (const float*)d_in[3];
    const float* b2 = (const float*)d_in[4];
    const float* Wq = (const float*)d_in[5];
    const float* bq = (const float*)d_in[6];
    const float* Wh = (const float*)d_in[7];
    const float* bh = (const float*)d_in[8];
    float* out = (float*)d_out;

    // out = bh (also clears the 0xAA poison)
    init_out<<<1, 32>>>(out, bh);

    // whole network in one kernel: 256 CTAs x 128 threads, 32 rows each
    fused_net<<<NROWS / BM, 128>>>(X, W1, b1, W2, b2, Wq, bq, Wh, out);
}